// round 1
// baseline (speedup 1.0000x reference)
#include <cuda_runtime.h>
#include <math.h>

#define B_ 16
#define N_ 1024
#define FIN_ 64
#define H_ 256
#define NEGV (-9e15f)

// ---------------- scratch (static device globals; no allocation) ----------------
__device__ float g_x  [B_ * N_ * H_];   // embed output / layer inputs
__device__ float g_x2 [B_ * N_ * H_];   // layer1 output
__device__ float g_h  [B_ * N_ * H_];   // per-layer h = x @ W
__device__ float g_s1 [B_ * N_];
__device__ float g_s2 [B_ * N_];
__device__ float g_m  [B_ * N_];
__device__ float g_rl [B_ * N_];        // 1 / softmax denominator
__device__ float g_psum[B_ * 8 * H_];
__device__ float g_pmax[B_ * 8 * H_];

// ---------------- generic fp32 GEMM: C[M,N] = A[M,K] @ Bm[K,N] (+bias, relu) ----
// BM=BN=128, BK=16, 256 threads, 8x8 per thread.
__global__ void gemm128(const float* __restrict__ A, const float* __restrict__ Bm,
                        const float* __restrict__ bias, float* __restrict__ C,
                        int M, int Nn, int K, int relu)
{
    __shared__ float As[16][132];
    __shared__ float Bs[16][132];
    const int tid = threadIdx.x;
    const int tx = tid & 15, ty = tid >> 4;
    const int m0 = blockIdx.y * 128, n0 = blockIdx.x * 128;

    float acc[8][8];
#pragma unroll
    for (int i = 0; i < 8; i++)
#pragma unroll
        for (int j = 0; j < 8; j++) acc[i][j] = 0.f;

    for (int k0 = 0; k0 < K; k0 += 16) {
#pragma unroll
        for (int l = 0; l < 2; l++) {
            int q = tid + l * 256;             // 512 float4 loads cover 128x16
            int row = q >> 2, c = (q & 3) * 4;
            float4 v = *(const float4*)(A + (size_t)(m0 + row) * K + k0 + c);
            As[c + 0][row] = v.x; As[c + 1][row] = v.y;
            As[c + 2][row] = v.z; As[c + 3][row] = v.w;
        }
#pragma unroll
        for (int l = 0; l < 2; l++) {
            int q = tid + l * 256;             // 16x128
            int row = q >> 5, c = (q & 31) * 4;
            *(float4*)&Bs[row][c] =
                *(const float4*)(Bm + (size_t)(k0 + row) * Nn + n0 + c);
        }
        __syncthreads();
#pragma unroll
        for (int kk = 0; kk < 16; kk++) {
            float af[8], bf[8];
            *(float4*)&af[0] = *(float4*)&As[kk][ty * 8];
            *(float4*)&af[4] = *(float4*)&As[kk][ty * 8 + 4];
            *(float4*)&bf[0] = *(float4*)&Bs[kk][tx * 8];
            *(float4*)&bf[4] = *(float4*)&Bs[kk][tx * 8 + 4];
#pragma unroll
            for (int i = 0; i < 8; i++)
#pragma unroll
                for (int j = 0; j < 8; j++)
                    acc[i][j] = fmaf(af[i], bf[j], acc[i][j]);
        }
        __syncthreads();
    }

#pragma unroll
    for (int i = 0; i < 8; i++) {
        int r = m0 + ty * 8 + i;
        float* op = C + (size_t)r * Nn + n0 + tx * 8;
#pragma unroll
        for (int j = 0; j < 8; j++) {
            float v = acc[i][j];
            if (bias) v += bias[n0 + tx * 8 + j];
            if (relu) v = fmaxf(v, 0.f);
            acc[i][j] = v;
        }
        *(float4*)op       = *(float4*)&acc[i][0];
        *(float4*)(op + 4) = *(float4*)&acc[i][4];
    }
}

// ---------------- s1/s2: per-row dot of h with a1/a2 ----------------------------
__global__ void s12_kernel(const float* __restrict__ h, const float* __restrict__ a1,
                           const float* __restrict__ a2,
                           float* __restrict__ s1, float* __restrict__ s2)
{
    __shared__ float a1s[H_], a2s[H_];
    const int tid = threadIdx.x;
    a1s[tid] = a1[tid];
    a2s[tid] = a2[tid];
    __syncthreads();
    const int w = tid >> 5, lane = tid & 31;
    const int row = blockIdx.x * 8 + w;
    const float* hp = h + (size_t)row * H_ + lane * 8;
    float d1 = 0.f, d2 = 0.f;
#pragma unroll
    for (int t = 0; t < 8; t++) {
        float v = hp[t];
        d1 = fmaf(v, a1s[lane * 8 + t], d1);
        d2 = fmaf(v, a2s[lane * 8 + t], d2);
    }
#pragma unroll
    for (int o = 16; o > 0; o >>= 1) {
        d1 += __shfl_xor_sync(0xffffffffu, d1, o);
        d2 += __shfl_xor_sync(0xffffffffu, d2, o);
    }
    if (lane == 0) { s1[row] = d1; s2[row] = d2; }
}

// ---------------- softmax stats pass: per row i, m_i and 1/l_i ------------------
__global__ void stat_kernel(const float* __restrict__ adj, const float* __restrict__ s1,
                            const float* __restrict__ s2,
                            float* __restrict__ gm, float* __restrict__ grl)
{
    __shared__ float s2s[N_];
    const int b = blockIdx.y;
    const int tid = threadIdx.x;
    for (int i = tid; i < N_; i += 256) s2s[i] = s2[b * N_ + i];
    __syncthreads();
    const int w = tid >> 5, lane = tid & 31;
    const int i = blockIdx.x * 8 + w;
    const int row = b * N_ + i;
    const float s1i = s1[row];
    const float* ar = adj + (size_t)row * N_;

    float mloc = NEGV;
    for (int j = lane; j < N_; j += 32) {
        float a = ar[j];
        float x = s1i + s2s[j];
        float e = fmaxf(x, 0.2f * x);
        float sc = (a > 0.f) ? e : NEGV;
        mloc = fmaxf(mloc, sc);
    }
#pragma unroll
    for (int o = 16; o > 0; o >>= 1)
        mloc = fmaxf(mloc, __shfl_xor_sync(0xffffffffu, mloc, o));

    float lloc = 0.f;
    for (int j = lane; j < N_; j += 32) {
        float a = ar[j];
        float x = s1i + s2s[j];
        float e = fmaxf(x, 0.2f * x);
        float sc = (a > 0.f) ? e : NEGV;
        lloc += __expf(sc - mloc);
    }
#pragma unroll
    for (int o = 16; o > 0; o >>= 1)
        lloc += __shfl_xor_sync(0xffffffffu, lloc, o);

    if (lane == 0) { gm[row] = mloc; grl[row] = 1.f / lloc; }
}

// ---------------- attention GEMM: out = softmax(masked e) @ h, relu -------------
// A-tile (128x16 of probabilities) generated on the fly from adj/s1/s2/m/rl.
__global__ void att_kernel(const float* __restrict__ adj, const float* __restrict__ h,
                           const float* __restrict__ s1, const float* __restrict__ s2,
                           const float* __restrict__ m, const float* __restrict__ rl,
                           float* __restrict__ out)
{
    __shared__ float Ps[16][132];
    __shared__ float Hs[16][132];
    __shared__ float s1s[128], ms[128], rls[128];
    const int b = blockIdx.z;
    const int i0 = blockIdx.y * 128, n0 = blockIdx.x * 128;
    const int tid = threadIdx.x;
    const int tx = tid & 15, ty = tid >> 4;

    if (tid < 128) {
        int r = b * N_ + i0 + tid;
        s1s[tid] = s1[r];
        ms[tid]  = m[r];
        rls[tid] = rl[r];
    }
    __syncthreads();

    float acc[8][8];
#pragma unroll
    for (int i = 0; i < 8; i++)
#pragma unroll
        for (int j = 0; j < 8; j++) acc[i][j] = 0.f;

    for (int k0 = 0; k0 < N_; k0 += 16) {
#pragma unroll
        for (int l = 0; l < 2; l++) {
            int q = tid + l * 256;
            int row = q >> 2, c = (q & 3) * 4;
            float4 av = *(const float4*)(adj + (size_t)(b * N_ + i0 + row) * N_ + k0 + c);
            float4 sv = *(const float4*)(s2 + b * N_ + k0 + c);
            float s1r = s1s[row], mr = ms[row], rr = rls[row];
            float aa[4] = { av.x, av.y, av.z, av.w };
            float ss[4] = { sv.x, sv.y, sv.z, sv.w };
#pragma unroll
            for (int t = 0; t < 4; t++) {
                float x = s1r + ss[t];
                float e = fmaxf(x, 0.2f * x);
                float sc = (aa[t] > 0.f) ? e : NEGV;
                Ps[c + t][row] = __expf(sc - mr) * rr;
            }
        }
#pragma unroll
        for (int l = 0; l < 2; l++) {
            int q = tid + l * 256;
            int row = q >> 5, c = (q & 31) * 4;
            *(float4*)&Hs[row][c] =
                *(const float4*)(h + (size_t)(b * N_ + k0 + row) * H_ + n0 + c);
        }
        __syncthreads();
#pragma unroll
        for (int kk = 0; kk < 16; kk++) {
            float af[8], bf[8];
            *(float4*)&af[0] = *(float4*)&Ps[kk][ty * 8];
            *(float4*)&af[4] = *(float4*)&Ps[kk][ty * 8 + 4];
            *(float4*)&bf[0] = *(float4*)&Hs[kk][tx * 8];
            *(float4*)&bf[4] = *(float4*)&Hs[kk][tx * 8 + 4];
#pragma unroll
            for (int i = 0; i < 8; i++)
#pragma unroll
                for (int j = 0; j < 8; j++)
                    acc[i][j] = fmaf(af[i], bf[j], acc[i][j]);
        }
        __syncthreads();
    }

#pragma unroll
    for (int i = 0; i < 8; i++) {
        int r = i0 + ty * 8 + i;
        float* op = out + (size_t)(b * N_ + r) * H_ + n0 + tx * 8;
#pragma unroll
        for (int j = 0; j < 8; j++) acc[i][j] = fmaxf(acc[i][j], 0.f);  // relu
        *(float4*)op       = *(float4*)&acc[i][0];
        *(float4*)(op + 4) = *(float4*)&acc[i][4];
    }
}

// ---------------- pooling (partial over N chunks) -------------------------------
__global__ void pool_partial(const float* __restrict__ x,
                             float* __restrict__ psum, float* __restrict__ pmax)
{
    const int b = blockIdx.y, ch = blockIdx.x, c = threadIdx.x;
    const float* p = x + (size_t)(b * N_ + ch * 128) * H_ + c;
    float s = 0.f, mx = -1e30f;
#pragma unroll 4
    for (int n = 0; n < 128; n++) {
        float v = p[(size_t)n * H_];
        s += v;
        mx = fmaxf(mx, v);
    }
    psum[(b * 8 + ch) * H_ + c] = s;
    pmax[(b * 8 + ch) * H_ + c] = mx;
}

// ---------------- pool finalize + 2-layer MLP -----------------------------------
__global__ void final_kernel(const float* __restrict__ psum, const float* __restrict__ pmax,
                             const float* __restrict__ W1, const float* __restrict__ b1,
                             const float* __restrict__ W2, const float* __restrict__ b2,
                             float* __restrict__ gout)
{
    __shared__ float gv[H_], g1[H_];
    const int b = blockIdx.x, c = threadIdx.x;
    float s = 0.f, mx = -1e30f;
#pragma unroll
    for (int ch = 0; ch < 8; ch++) {
        s += psum[(b * 8 + ch) * H_ + c];
        mx = fmaxf(mx, pmax[(b * 8 + ch) * H_ + c]);
    }
    gv[c] = s * (1.0f / N_) + mx;
    __syncthreads();
    float a = b1[c];
    for (int k = 0; k < H_; k++) a = fmaf(gv[k], W1[k * H_ + c], a);
    g1[c] = fmaxf(a, 0.f);
    __syncthreads();
    float a2 = b2[c];
    for (int k = 0; k < H_; k++) a2 = fmaf(g1[k], W2[k * H_ + c], a2);
    gout[b * H_ + c] = a2;
}

// ---------------- launch --------------------------------------------------------
extern "C" void kernel_launch(void* const* d_in, const int* in_sizes, int n_in,
                              void* d_out, int out_size)
{
    const float* nf    = (const float*)d_in[0];
    const float* adj   = (const float*)d_in[1];
    const float* embW  = (const float*)d_in[2];
    const float* embb  = (const float*)d_in[3];
    const float* W0    = (const float*)d_in[4];
    const float* a1_0  = (const float*)d_in[5];
    const float* a2_0  = (const float*)d_in[6];
    const float* W1    = (const float*)d_in[7];
    const float* a1_1  = (const float*)d_in[8];
    const float* a2_1  = (const float*)d_in[9];
    const float* gpW1  = (const float*)d_in[10];
    const float* gpb1  = (const float*)d_in[11];
    const float* gpW2  = (const float*)d_in[12];
    const float* gpb2  = (const float*)d_in[13];

    float* out  = (float*)d_out;                 // x region [16,1024,256]
    float* outg = out + (size_t)B_ * N_ * H_;    // g region [16,256]

    float *px, *px2, *ph, *ps1, *ps2, *pm, *prl, *ppsum, *ppmax;
    cudaGetSymbolAddress((void**)&px,    g_x);
    cudaGetSymbolAddress((void**)&px2,   g_x2);
    cudaGetSymbolAddress((void**)&ph,    g_h);
    cudaGetSymbolAddress((void**)&ps1,   g_s1);
    cudaGetSymbolAddress((void**)&ps2,   g_s2);
    cudaGetSymbolAddress((void**)&pm,    g_m);
    cudaGetSymbolAddress((void**)&prl,   g_rl);
    cudaGetSymbolAddress((void**)&ppsum, g_psum);
    cudaGetSymbolAddress((void**)&ppmax, g_pmax);

    const int M = B_ * N_;
    dim3 gemmGrid(H_ / 128, M / 128);
    dim3 attGrid(H_ / 128, N_ / 128, B_);
    dim3 statGrid(N_ / 8, B_);

    // embed: x = nf @ emb_W + emb_b
    gemm128<<<gemmGrid, 256>>>(nf, embW, embb, px, M, H_, FIN_, 0);

    // ---- GAT layer 1 ----
    gemm128<<<gemmGrid, 256>>>(px, W0, nullptr, ph, M, H_, H_, 0);
    s12_kernel<<<M / 8, 256>>>(ph, a1_0, a2_0, ps1, ps2);
    stat_kernel<<<statGrid, 256>>>(adj, ps1, ps2, pm, prl);
    att_kernel<<<attGrid, 256>>>(adj, ph, ps1, ps2, pm, prl, px2);

    // ---- GAT layer 2 (writes x directly into d_out) ----
    gemm128<<<gemmGrid, 256>>>(px2, W1, nullptr, ph, M, H_, H_, 0);
    s12_kernel<<<M / 8, 256>>>(ph, a1_1, a2_1, ps1, ps2);
    stat_kernel<<<statGrid, 256>>>(adj, ps1, ps2, pm, prl);
    att_kernel<<<attGrid, 256>>>(adj, ph, ps1, ps2, pm, prl, out);

    // ---- pooling + MLP head ----
    pool_partial<<<dim3(8, B_), 256>>>(out, ppsum, ppmax);
    final_kernel<<<B_, 256>>>(ppsum, ppmax, gpW1, gpb1, gpW2, gpb2, outg);
}

// round 3
// speedup vs baseline: 1.7206x; 1.7206x over previous
#include <cuda_runtime.h>
#include <cuda_fp16.h>
#include <cstdint>

#define B_ 16
#define N_ 1024
#define FIN_ 64
#define H_ 256
#define NEGV (-9e15f)

// ===================== scratch (static device globals) =====================
__device__ __half g_nf16 [B_ * N_ * FIN_];
__device__ __half g_x16a [B_ * N_ * H_];
__device__ __half g_x16b [B_ * N_ * H_];
__device__ __half g_h16  [B_ * N_ * H_];     // h natural layout [b][j][c]
__device__ __half g_wemb16[FIN_ * H_];       // natural [k][c]
__device__ __half g_w016 [H_ * H_];
__device__ __half g_w116 [H_ * H_];
__device__ float  g_s1[B_ * N_], g_s2[B_ * N_], g_m[B_ * N_], g_rl[B_ * N_];
__device__ float  g_psum[B_ * 8 * H_], g_pmax[B_ * 8 * H_];

// ===================== mma/ldmatrix helpers (baseline PTX, sm_75+/80+) =====
__device__ __forceinline__ uint32_t smem_u32(const void* p) {
    uint32_t a;
    asm("{ .reg .u64 t; cvta.to.shared.u64 t, %1; cvt.u32.u64 %0, t; }" : "=r"(a) : "l"(p));
    return a;
}
__device__ __forceinline__ void ldsm_x4(uint32_t& r0, uint32_t& r1, uint32_t& r2,
                                        uint32_t& r3, uint32_t addr) {
    asm volatile("ldmatrix.sync.aligned.m8n8.x4.shared.b16 {%0,%1,%2,%3}, [%4];"
                 : "=r"(r0), "=r"(r1), "=r"(r2), "=r"(r3) : "r"(addr));
}
__device__ __forceinline__ void ldsm_x4_t(uint32_t& r0, uint32_t& r1, uint32_t& r2,
                                          uint32_t& r3, uint32_t addr) {
    asm volatile("ldmatrix.sync.aligned.m8n8.x4.trans.shared.b16 {%0,%1,%2,%3}, [%4];"
                 : "=r"(r0), "=r"(r1), "=r"(r2), "=r"(r3) : "r"(addr));
}
__device__ __forceinline__ void mma16816(float* d, const uint32_t* a, const uint32_t* b) {
    asm volatile("mma.sync.aligned.m16n8k16.row.col.f32.f16.f16.f32 "
                 "{%0,%1,%2,%3}, {%4,%5,%6,%7}, {%8,%9}, {%0,%1,%2,%3};"
                 : "+f"(d[0]), "+f"(d[1]), "+f"(d[2]), "+f"(d[3])
                 : "r"(a[0]), "r"(a[1]), "r"(a[2]), "r"(a[3]), "r"(b[0]), "r"(b[1]));
}

// ===================== prep: fp16 conversion (no transposes) =====================
__global__ void prep_kernel(const float* __restrict__ nf, const float* __restrict__ embW,
                            const float* __restrict__ W0, const float* __restrict__ W1)
{
    const int NF_E = B_ * N_ * FIN_;
    const int EW_E = FIN_ * H_;
    const int W_E  = H_ * H_;
    const int TOT  = NF_E + EW_E + 2 * W_E;
    for (int idx = blockIdx.x * blockDim.x + threadIdx.x; idx < TOT;
         idx += gridDim.x * blockDim.x) {
        if (idx < NF_E) g_nf16[idx] = __float2half(nf[idx]);
        else if (idx < NF_E + EW_E) g_wemb16[idx - NF_E] = __float2half(embW[idx - NF_E]);
        else if (idx < NF_E + EW_E + W_E) g_w016[idx - NF_E - EW_E] = __float2half(W0[idx - NF_E - EW_E]);
        else g_w116[idx - NF_E - EW_E - W_E] = __float2half(W1[idx - NF_E - EW_E - W_E]);
    }
}

// ===================== hgemm via mma: C[16384,256] = A[16384,K] @ Bw[K,256] ======
// MODE 0 (embed): +bias -> fp16 out16
// MODE 1 (hidden): fp16 h -> out16 (natural layout), s1/s2 dots fp32
template <int KDIM, int MODE>
__global__ void __launch_bounds__(256) hgemm_mma(
    const __half* __restrict__ A, const __half* __restrict__ Bw,
    const float* __restrict__ v1, const float* __restrict__ v2,
    __half* __restrict__ out16, float* __restrict__ s1o, float* __restrict__ s2o)
{
    __shared__ __half As[64][40];
    __shared__ __half Bs[32][264];
    __shared__ float vb1[H_], vb2[H_];
    __shared__ float s1b[64], s2b[64];

    const int tid = threadIdx.x, wid = tid >> 5, lane = tid & 31;
    const int wm = wid >> 2, wn = wid & 3;          // 2 x 4 warp grid
    const int row0 = blockIdx.x * 64;

    vb1[tid] = v1[tid];
    if (MODE == 1) vb2[tid] = v2[tid];
    if (tid < 64) { s1b[tid] = 0.f; s2b[tid] = 0.f; }

    const uint32_t asu = smem_u32(&As[0][0]);
    const uint32_t bsu = smem_u32(&Bs[0][0]);

    float acc[2][8][4];
#pragma unroll
    for (int i = 0; i < 2; i++)
#pragma unroll
        for (int j = 0; j < 8; j++)
#pragma unroll
            for (int t = 0; t < 4; t++) acc[i][j][t] = 0.f;

    const int arow = tid >> 2, aseg = tid & 3;       // A: 64 rows x 32 halfs
    const int brow = tid >> 3, bseg = (tid & 7) * 32; // B: 32 rows x 256 halfs

    for (int k0 = 0; k0 < KDIM; k0 += 32) {
        __syncthreads();
        {   // A tile
            uint4 v = *(const uint4*)(A + (size_t)(row0 + arow) * KDIM + k0 + aseg * 8);
            *(uint4*)&As[arow][aseg * 8] = v;
        }
        {   // B tile (natural [k][n])
            const uint4* src = (const uint4*)(Bw + (size_t)(k0 + brow) * H_ + bseg);
#pragma unroll
            for (int u = 0; u < 4; u++) *(uint4*)&Bs[brow][bseg + u * 8] = src[u];
        }
        __syncthreads();

#pragma unroll
        for (int ksi = 0; ksi < 2; ksi++) {
            const int ksl = ksi * 16;
            uint32_t af[2][4];
#pragma unroll
            for (int mf = 0; mf < 2; mf++) {
                int r = wm * 32 + mf * 16 + (lane & 15);
                int c = ksl + (lane >> 4) * 8;
                ldsm_x4(af[mf][0], af[mf][1], af[mf][2], af[mf][3],
                        asu + (r * 40 + c) * 2);
            }
            uint32_t bf[8][2];
#pragma unroll
            for (int ng = 0; ng < 4; ng++) {
                int r = ksl + (lane & 15);
                int c = wn * 64 + ng * 16 + (lane >> 4) * 8;
                ldsm_x4_t(bf[ng * 2][0], bf[ng * 2][1], bf[ng * 2 + 1][0], bf[ng * 2 + 1][1],
                          bsu + (r * 264 + c) * 2);
            }
#pragma unroll
            for (int mf = 0; mf < 2; mf++)
#pragma unroll
                for (int nf = 0; nf < 8; nf++)
                    mma16816(acc[mf][nf], af[mf], bf[nf]);
        }
    }

    // ---------------- epilogue ----------------
    const int r1 = lane >> 2, cq = (lane & 3) * 2;
#pragma unroll
    for (int mf = 0; mf < 2; mf++) {
#pragma unroll
        for (int rr = 0; rr < 2; rr++) {
            const int rloc = wm * 32 + mf * 16 + r1 + rr * 8;
            const int grow = row0 + rloc;
            float p1 = 0.f, p2 = 0.f;
#pragma unroll
            for (int nf = 0; nf < 8; nf++) {
                const int col = wn * 64 + nf * 8 + cq;
                float e0 = acc[mf][nf][rr * 2], e1 = acc[mf][nf][rr * 2 + 1];
                if (MODE == 0) { e0 += vb1[col]; e1 += vb1[col + 1]; }
                else {
                    p1 = fmaf(e0, vb1[col], fmaf(e1, vb1[col + 1], p1));
                    p2 = fmaf(e0, vb2[col], fmaf(e1, vb2[col + 1], p2));
                }
                ((__half2*)out16)[((size_t)grow * H_ + col) >> 1] = __floats2half2_rn(e0, e1);
            }
            if (MODE == 1) {
                p1 += __shfl_xor_sync(0xffffffffu, p1, 1);
                p1 += __shfl_xor_sync(0xffffffffu, p1, 2);
                p2 += __shfl_xor_sync(0xffffffffu, p2, 1);
                p2 += __shfl_xor_sync(0xffffffffu, p2, 2);
                if ((lane & 3) == 0) {
                    atomicAdd(&s1b[rloc], p1);
                    atomicAdd(&s2b[rloc], p2);
                }
            }
        }
    }
    if (MODE == 1) {
        __syncthreads();
        if (tid < 64) { s1o[row0 + tid] = s1b[tid]; s2o[row0 + tid] = s2b[tid]; }
    }
}

// ===================== softmax stats (R1 proven, two-pass) =====================
__global__ void stat_kernel(const float* __restrict__ adj, const float* __restrict__ s1,
                            const float* __restrict__ s2,
                            float* __restrict__ gm, float* __restrict__ grl)
{
    __shared__ float s2s[N_];
    const int b = blockIdx.y;
    const int tid = threadIdx.x;
    for (int i = tid; i < N_; i += 256) s2s[i] = s2[b * N_ + i];
    __syncthreads();
    const int w = tid >> 5, lane = tid & 31;
    const int i = blockIdx.x * 8 + w;
    const int row = b * N_ + i;
    const float s1i = s1[row];
    const float* ar = adj + (size_t)row * N_;

    float mloc = NEGV;
    for (int j = lane; j < N_; j += 32) {
        float a = ar[j];
        float x = s1i + s2s[j];
        float e = fmaxf(x, 0.2f * x);
        float sc = (a > 0.f) ? e : NEGV;
        mloc = fmaxf(mloc, sc);
    }
#pragma unroll
    for (int o = 16; o > 0; o >>= 1)
        mloc = fmaxf(mloc, __shfl_xor_sync(0xffffffffu, mloc, o));

    float lloc = 0.f;
    for (int j = lane; j < N_; j += 32) {
        float a = ar[j];
        float x = s1i + s2s[j];
        float e = fmaxf(x, 0.2f * x);
        float sc = (a > 0.f) ? e : NEGV;
        lloc += __expf(sc - mloc);
    }
#pragma unroll
    for (int o = 16; o > 0; o >>= 1)
        lloc += __shfl_xor_sync(0xffffffffu, lloc, o);

    if (lane == 0) { gm[row] = mloc; grl[row] = 1.f / lloc; }
}

// ===================== attention via mma: out = softmax(e) @ h ==================
// P tile (64x32 fp16) generated on the fly; B = h16 natural [j][c] + ldmatrix.trans
__global__ void __launch_bounds__(256) att_mma(
    const float* __restrict__ adj, const __half* __restrict__ h16,
    const float* __restrict__ s1, const float* __restrict__ s2,
    const float* __restrict__ m, const float* __restrict__ rl,
    __half* __restrict__ out16, float* __restrict__ outf)
{
    __shared__ __half As[64][40];
    __shared__ __half Bs[32][264];
    __shared__ float s2s[N_];
    __shared__ float s1s[64], ms[64], rls[64];

    const int tid = threadIdx.x, wid = tid >> 5, lane = tid & 31;
    const int wm = wid >> 2, wn = wid & 3;
    const int b = blockIdx.y, i0 = blockIdx.x * 64;

    for (int i = tid; i < N_; i += 256) s2s[i] = s2[b * N_ + i];
    if (tid < 64) {
        int r = b * N_ + i0 + tid;
        s1s[tid] = s1[r]; ms[tid] = m[r]; rls[tid] = rl[r];
    }
    __syncthreads();

    const uint32_t asu = smem_u32(&As[0][0]);
    const uint32_t bsu = smem_u32(&Bs[0][0]);

    float acc[2][8][4];
#pragma unroll
    for (int i = 0; i < 2; i++)
#pragma unroll
        for (int j = 0; j < 8; j++)
#pragma unroll
            for (int t = 0; t < 4; t++) acc[i][j][t] = 0.f;

    const int arow = tid >> 2, aseg = tid & 3;
    const int brow = tid >> 3, bseg = (tid & 7) * 32;
    const float s1r = s1s[arow], mr = ms[arow], rr_ = rls[arow];
    const float4* arp = (const float4*)(adj + (size_t)(b * N_ + i0 + arow) * N_);

    for (int k0 = 0; k0 < N_; k0 += 32) {
        __syncthreads();
        {   // P tile row arow, 8 j-values at k0 + aseg*8
            const int j = k0 + aseg * 8;
            float4 a0 = __ldg(arp + (j >> 2));
            float4 a1v = __ldg(arp + (j >> 2) + 1);
            float avs[8] = { a0.x, a0.y, a0.z, a0.w, a1v.x, a1v.y, a1v.z, a1v.w };
            float pv[8];
#pragma unroll
            for (int t = 0; t < 8; t++) {
                float x = s1r + s2s[j + t];
                float e = fmaxf(x, 0.2f * x);
                float sc = (avs[t] > 0.f) ? e : NEGV;
                pv[t] = __expf(sc - mr) * rr_;
            }
            __half2 h0 = __floats2half2_rn(pv[0], pv[1]);
            __half2 h1 = __floats2half2_rn(pv[2], pv[3]);
            __half2 h2 = __floats2half2_rn(pv[4], pv[5]);
            __half2 h3 = __floats2half2_rn(pv[6], pv[7]);
            uint4 w4 = { *(uint32_t*)&h0, *(uint32_t*)&h1, *(uint32_t*)&h2, *(uint32_t*)&h3 };
            *(uint4*)&As[arow][aseg * 8] = w4;
        }
        {   // H tile: rows j = k0+brow, cols bseg..bseg+31
            const uint4* src = (const uint4*)(h16 + (size_t)(b * N_ + k0 + brow) * H_ + bseg);
#pragma unroll
            for (int u = 0; u < 4; u++) *(uint4*)&Bs[brow][bseg + u * 8] = src[u];
        }
        __syncthreads();

#pragma unroll
        for (int ksi = 0; ksi < 2; ksi++) {
            const int ksl = ksi * 16;
            uint32_t af[2][4];
#pragma unroll
            for (int mf = 0; mf < 2; mf++) {
                int r = wm * 32 + mf * 16 + (lane & 15);
                int c = ksl + (lane >> 4) * 8;
                ldsm_x4(af[mf][0], af[mf][1], af[mf][2], af[mf][3],
                        asu + (r * 40 + c) * 2);
            }
            uint32_t bf[8][2];
#pragma unroll
            for (int ng = 0; ng < 4; ng++) {
                int r = ksl + (lane & 15);
                int c = wn * 64 + ng * 16 + (lane >> 4) * 8;
                ldsm_x4_t(bf[ng * 2][0], bf[ng * 2][1], bf[ng * 2 + 1][0], bf[ng * 2 + 1][1],
                          bsu + (r * 264 + c) * 2);
            }
#pragma unroll
            for (int mf = 0; mf < 2; mf++)
#pragma unroll
                for (int nf = 0; nf < 8; nf++)
                    mma16816(acc[mf][nf], af[mf], bf[nf]);
        }
    }

    // ---------------- epilogue: relu, write fp16 or fp32 ----------------
    const int r1 = lane >> 2, cq = (lane & 3) * 2;
#pragma unroll
    for (int mf = 0; mf < 2; mf++) {
#pragma unroll
        for (int rr = 0; rr < 2; rr++) {
            const int grow = b * N_ + i0 + wm * 32 + mf * 16 + r1 + rr * 8;
#pragma unroll
            for (int nf = 0; nf < 8; nf++) {
                const int col = wn * 64 + nf * 8 + cq;
                float e0 = fmaxf(acc[mf][nf][rr * 2], 0.f);
                float e1 = fmaxf(acc[mf][nf][rr * 2 + 1], 0.f);
                if (outf) {
                    float2 v = { e0, e1 };
                    *(float2*)(outf + (size_t)grow * H_ + col) = v;
                } else {
                    ((__half2*)out16)[((size_t)grow * H_ + col) >> 1] = __floats2half2_rn(e0, e1);
                }
            }
        }
    }
}

// ===================== pooling + MLP head (R1 proven) =====================
__global__ void pool_partial(const float* __restrict__ x)
{
    const int b = blockIdx.y, ch = blockIdx.x, c = threadIdx.x;
    const float* p = x + (size_t)(b * N_ + ch * 128) * H_ + c;
    float s = 0.f, mx = -1e30f;
#pragma unroll 4
    for (int n = 0; n < 128; n++) {
        float v = p[(size_t)n * H_];
        s += v; mx = fmaxf(mx, v);
    }
    g_psum[(b * 8 + ch) * H_ + c] = s;
    g_pmax[(b * 8 + ch) * H_ + c] = mx;
}

__global__ void final_kernel(const float* __restrict__ W1, const float* __restrict__ b1,
                             const float* __restrict__ W2, const float* __restrict__ b2,
                             float* __restrict__ gout)
{
    __shared__ float gv[H_], g1[H_];
    const int b = blockIdx.x, c = threadIdx.x;
    float s = 0.f, mx = -1e30f;
#pragma unroll
    for (int ch = 0; ch < 8; ch++) {
        s += g_psum[(b * 8 + ch) * H_ + c];
        mx = fmaxf(mx, g_pmax[(b * 8 + ch) * H_ + c]);
    }
    gv[c] = s * (1.0f / N_) + mx;
    __syncthreads();
    float a = b1[c];
    for (int k = 0; k < H_; k++) a = fmaf(gv[k], W1[k * H_ + c], a);
    g1[c] = fmaxf(a, 0.f);
    __syncthreads();
    float a2 = b2[c];
    for (int k = 0; k < H_; k++) a2 = fmaf(g1[k], W2[k * H_ + c], a2);
    gout[b * H_ + c] = a2;
}

// ===================== launch =====================
extern "C" void kernel_launch(void* const* d_in, const int* in_sizes, int n_in,
                              void* d_out, int out_size)
{
    const float* nf   = (const float*)d_in[0];
    const float* adj  = (const float*)d_in[1];
    const float* embW = (const float*)d_in[2];
    const float* embb = (const float*)d_in[3];
    const float* W0   = (const float*)d_in[4];
    const float* a1_0 = (const float*)d_in[5];
    const float* a2_0 = (const float*)d_in[6];
    const float* W1   = (const float*)d_in[7];
    const float* a1_1 = (const float*)d_in[8];
    const float* a2_1 = (const float*)d_in[9];
    const float* gpW1 = (const float*)d_in[10];
    const float* gpb1 = (const float*)d_in[11];
    const float* gpW2 = (const float*)d_in[12];
    const float* gpb2 = (const float*)d_in[13];

    float* out  = (float*)d_out;
    float* outg = out + (size_t)B_ * N_ * H_;

    __half *pnf16, *px16a, *px16b, *ph16, *pwemb, *pw0, *pw1;
    float *ps1, *ps2, *pm, *prl;
    cudaGetSymbolAddress((void**)&pnf16, g_nf16);
    cudaGetSymbolAddress((void**)&px16a, g_x16a);
    cudaGetSymbolAddress((void**)&px16b, g_x16b);
    cudaGetSymbolAddress((void**)&ph16,  g_h16);
    cudaGetSymbolAddress((void**)&pwemb, g_wemb16);
    cudaGetSymbolAddress((void**)&pw0,   g_w016);
    cudaGetSymbolAddress((void**)&pw1,   g_w116);
    cudaGetSymbolAddress((void**)&ps1,   g_s1);
    cudaGetSymbolAddress((void**)&ps2,   g_s2);
    cudaGetSymbolAddress((void**)&pm,    g_m);
    cudaGetSymbolAddress((void**)&prl,   g_rl);

    const int M = B_ * N_;

    prep_kernel<<<1024, 256>>>(nf, embW, W0, W1);

    // embed: x16a = nf @ embW + b
    hgemm_mma<FIN_, 0><<<M / 64, 256>>>(pnf16, pwemb, embb, nullptr,
                                        px16a, nullptr, nullptr);
    // ---- layer 1 ----
    hgemm_mma<H_, 1><<<M / 64, 256>>>(px16a, pw0, a1_0, a2_0, ph16, ps1, ps2);
    stat_kernel<<<dim3(N_ / 8, B_), 256>>>(adj, ps1, ps2, pm, prl);
    att_mma<<<dim3(N_ / 64, B_), 256>>>(adj, ph16, ps1, ps2, pm, prl, px16b, nullptr);

    // ---- layer 2 ----
    hgemm_mma<H_, 1><<<M / 64, 256>>>(px16b, pw1, a1_1, a2_1, ph16, ps1, ps2);
    stat_kernel<<<dim3(N_ / 8, B_), 256>>>(adj, ps1, ps2, pm, prl);
    att_mma<<<dim3(N_ / 64, B_), 256>>>(adj, ph16, ps1, ps2, pm, prl, nullptr, out);

    // ---- pooling + MLP head ----
    pool_partial<<<dim3(8, B_), 256>>>(out);
    final_kernel<<<B_, 256>>>(gpW1, gpb1, gpW2, gpb2, outg);
}

// round 4
// speedup vs baseline: 2.6423x; 1.5357x over previous
#include <cuda_runtime.h>
#include <cuda_fp16.h>
#include <cstdint>

#define B_ 16
#define N_ 1024
#define FIN_ 64
#define H_ 256
#define NEGV (-9e15f)

// ===================== scratch (static device globals) =====================
__device__ __half    g_x16b [B_ * N_ * H_];   // layer1 output (fp16)
__device__ __half    g_h16  [B_ * N_ * H_];   // h natural layout [b][j][c]
__device__ __half    g_wf16 [FIN_ * H_];      // fused emb@W0 (fp16)
__device__ float     g_bf   [H_];             // fused bias emb_b@W0
__device__ __half    g_w116 [H_ * H_];
__device__ uint32_t  g_mask [B_ * N_ * 32];   // 1 bit per adj entry
__device__ float     g_s1[B_ * N_], g_s2[B_ * N_], g_m[B_ * N_], g_rl[B_ * N_];
__device__ float     g_psum[B_ * 8 * H_], g_pmax[B_ * 8 * H_];

// ===================== mma/ldmatrix helpers (baseline PTX) =====================
__device__ __forceinline__ uint32_t smem_u32(const void* p) {
    uint32_t a;
    asm("{ .reg .u64 t; cvta.to.shared.u64 t, %1; cvt.u32.u64 %0, t; }" : "=r"(a) : "l"(p));
    return a;
}
__device__ __forceinline__ void ldsm_x4(uint32_t& r0, uint32_t& r1, uint32_t& r2,
                                        uint32_t& r3, uint32_t addr) {
    asm volatile("ldmatrix.sync.aligned.m8n8.x4.shared.b16 {%0,%1,%2,%3}, [%4];"
                 : "=r"(r0), "=r"(r1), "=r"(r2), "=r"(r3) : "r"(addr));
}
__device__ __forceinline__ void ldsm_x4_t(uint32_t& r0, uint32_t& r1, uint32_t& r2,
                                          uint32_t& r3, uint32_t addr) {
    asm volatile("ldmatrix.sync.aligned.m8n8.x4.trans.shared.b16 {%0,%1,%2,%3}, [%4];"
                 : "=r"(r0), "=r"(r1), "=r"(r2), "=r"(r3) : "r"(addr));
}
__device__ __forceinline__ void mma16816(float* d, const uint32_t* a, const uint32_t* b) {
    asm volatile("mma.sync.aligned.m16n8k16.row.col.f32.f16.f16.f32 "
                 "{%0,%1,%2,%3}, {%4,%5,%6,%7}, {%8,%9}, {%0,%1,%2,%3};"
                 : "+f"(d[0]), "+f"(d[1]), "+f"(d[2]), "+f"(d[3])
                 : "r"(a[0]), "r"(a[1]), "r"(a[2]), "r"(a[3]), "r"(b[0]), "r"(b[1]));
}

// ===================== wfuse: Wf = emb@W0 (fp32), bf = emb_b@W0 =====================
__global__ void wfuse_kernel(const float* __restrict__ embW, const float* __restrict__ embb,
                             const float* __restrict__ W0)
{
    __shared__ float row[H_];
    const int f = blockIdx.x, o = threadIdx.x;
    row[o] = (f < FIN_) ? embW[f * H_ + o] : embb[o];
    __syncthreads();
    float acc = 0.f;
#pragma unroll 8
    for (int h = 0; h < H_; h++) acc = fmaf(row[h], W0[h * H_ + o], acc);
    if (f < FIN_) g_wf16[f * H_ + o] = __float2half(acc);
    else          g_bf[o] = acc;
}

__global__ void prepw1_kernel(const float* __restrict__ W1)
{
    int i = blockIdx.x * 256 + threadIdx.x;
    g_w116[i] = __float2half(W1[i]);
}

// ===================== mask build: adj fp32 -> bitmask =====================
__global__ void maskbuild_kernel(const float* __restrict__ adj)
{
    const int wid = threadIdx.x >> 5, lane = threadIdx.x & 31;
    const int row = blockIdx.x * 8 + wid;              // 0..16383
    const float* ar = adj + (size_t)row * N_;
#pragma unroll
    for (int it = 0; it < 32; it++) {
        float a = ar[it * 32 + lane];
        unsigned w = __ballot_sync(0xffffffffu, a > 0.f);
        if (lane == 0) g_mask[row * 32 + it] = w;
    }
}

// ===================== hgemm: C[16384,256] = A[16384,K] @ Bw[K,256] (+bias) =====
// epilogue: h fp16 out + s1/s2 dots (fp32)
template <int KDIM, bool AFP32>
__global__ void __launch_bounds__(256, 2) hgemm_mma(
    const void* __restrict__ Araw, const __half* __restrict__ Bw,
    const float* __restrict__ bias, const float* __restrict__ a1v,
    const float* __restrict__ a2v,
    __half* __restrict__ out16, float* __restrict__ s1o, float* __restrict__ s2o)
{
    __shared__ __half As[64][40];
    __shared__ __half Bs[32][264];
    __shared__ float vb1[H_], vb2[H_], bb[H_];
    __shared__ float s1b[64], s2b[64];

    const int tid = threadIdx.x, wid = tid >> 5, lane = tid & 31;
    const int wm = wid >> 2, wn = wid & 3;
    const int row0 = blockIdx.x * 64;

    vb1[tid] = a1v[tid];
    vb2[tid] = a2v[tid];
    bb[tid]  = bias ? bias[tid] : 0.f;
    if (tid < 64) { s1b[tid] = 0.f; s2b[tid] = 0.f; }

    const uint32_t asu = smem_u32(&As[0][0]);
    const uint32_t bsu = smem_u32(&Bs[0][0]);

    float acc[2][8][4];
#pragma unroll
    for (int i = 0; i < 2; i++)
#pragma unroll
        for (int j = 0; j < 8; j++)
#pragma unroll
            for (int t = 0; t < 4; t++) acc[i][j][t] = 0.f;

    const int arow = tid >> 2, aseg = tid & 3;        // A: 64 rows x 32
    const int brow = tid >> 3, bseg = (tid & 7) * 32; // B: 32 rows x 256

    float4 aF0, aF1;   // fp32 A prefetch
    uint4  aPk;        // fp16 A prefetch
    uint4  bPk[4];     // B prefetch

    auto loadA = [&](int k0) {
        if (AFP32) {
            const float* A = (const float*)Araw;
            const float* p = A + (size_t)(row0 + arow) * KDIM + k0 + aseg * 8;
            aF0 = *(const float4*)p;
            aF1 = *(const float4*)(p + 4);
        } else {
            const __half* A = (const __half*)Araw;
            aPk = *(const uint4*)(A + (size_t)(row0 + arow) * KDIM + k0 + aseg * 8);
        }
    };
    auto loadB = [&](int k0) {
        const uint4* src = (const uint4*)(Bw + (size_t)(k0 + brow) * H_ + bseg);
#pragma unroll
        for (int u = 0; u < 4; u++) bPk[u] = src[u];
    };
    auto stsTiles = [&]() {
        if (AFP32) {
            __half2 h0 = __floats2half2_rn(aF0.x, aF0.y);
            __half2 h1 = __floats2half2_rn(aF0.z, aF0.w);
            __half2 h2 = __floats2half2_rn(aF1.x, aF1.y);
            __half2 h3 = __floats2half2_rn(aF1.z, aF1.w);
            uint4 w4 = { *(uint32_t*)&h0, *(uint32_t*)&h1, *(uint32_t*)&h2, *(uint32_t*)&h3 };
            *(uint4*)&As[arow][aseg * 8] = w4;
        } else {
            *(uint4*)&As[arow][aseg * 8] = aPk;
        }
#pragma unroll
        for (int u = 0; u < 4; u++) *(uint4*)&Bs[brow][bseg + u * 8] = bPk[u];
    };
    auto compute = [&]() {
#pragma unroll
        for (int ksi = 0; ksi < 2; ksi++) {
            const int ksl = ksi * 16;
            uint32_t af[2][4];
#pragma unroll
            for (int mf = 0; mf < 2; mf++) {
                int r = wm * 32 + mf * 16 + (lane & 15);
                int c = ksl + (lane >> 4) * 8;
                ldsm_x4(af[mf][0], af[mf][1], af[mf][2], af[mf][3], asu + (r * 40 + c) * 2);
            }
            uint32_t bf[8][2];
#pragma unroll
            for (int ng = 0; ng < 4; ng++) {
                int r = ksl + (lane & 15);
                int c = wn * 64 + ng * 16 + (lane >> 4) * 8;
                ldsm_x4_t(bf[ng * 2][0], bf[ng * 2][1], bf[ng * 2 + 1][0], bf[ng * 2 + 1][1],
                          bsu + (r * 264 + c) * 2);
            }
#pragma unroll
            for (int mf = 0; mf < 2; mf++)
#pragma unroll
                for (int nf = 0; nf < 8; nf++)
                    mma16816(acc[mf][nf], af[mf], bf[nf]);
        }
    };

    constexpr int NK = KDIM / 32;
    loadA(0); loadB(0);
    __syncthreads();               // covers vb/bb/s1b init too
#pragma unroll
    for (int s = 0; s < NK; s++) {
        stsTiles();
        __syncthreads();
        if (s + 1 < NK) { loadA((s + 1) * 32); loadB((s + 1) * 32); }
        compute();
        __syncthreads();
    }

    // ---------------- epilogue ----------------
    const int r1 = lane >> 2, cq = (lane & 3) * 2;
#pragma unroll
    for (int mf = 0; mf < 2; mf++) {
#pragma unroll
        for (int rr = 0; rr < 2; rr++) {
            const int rloc = wm * 32 + mf * 16 + r1 + rr * 8;
            const int grow = row0 + rloc;
            float p1 = 0.f, p2 = 0.f;
#pragma unroll
            for (int nf = 0; nf < 8; nf++) {
                const int col = wn * 64 + nf * 8 + cq;
                float e0 = acc[mf][nf][rr * 2]     + bb[col];
                float e1 = acc[mf][nf][rr * 2 + 1] + bb[col + 1];
                p1 = fmaf(e0, vb1[col], fmaf(e1, vb1[col + 1], p1));
                p2 = fmaf(e0, vb2[col], fmaf(e1, vb2[col + 1], p2));
                ((__half2*)out16)[((size_t)grow * H_ + col) >> 1] = __floats2half2_rn(e0, e1);
            }
            p1 += __shfl_xor_sync(0xffffffffu, p1, 1);
            p1 += __shfl_xor_sync(0xffffffffu, p1, 2);
            p2 += __shfl_xor_sync(0xffffffffu, p2, 1);
            p2 += __shfl_xor_sync(0xffffffffu, p2, 2);
            if ((lane & 3) == 0) {
                atomicAdd(&s1b[rloc], p1);
                atomicAdd(&s2b[rloc], p2);
            }
        }
    }
    __syncthreads();
    if (tid < 64) { s1o[row0 + tid] = s1b[tid]; s2o[row0 + tid] = s2b[tid]; }
}

// ===================== stat: single pass, shift by upper bound m̂ =====================
// m̂_i = leaky(s1_i + max_j s2_j)  >= all scores (leaky monotone); softmax shift-invariant.
__global__ void stat_kernel(const float* __restrict__ s1, const float* __restrict__ s2,
                            float* __restrict__ gm, float* __restrict__ grl)
{
    __shared__ float s2s[N_];
    __shared__ float wmax[8];
    const int b = blockIdx.y, tid = threadIdx.x;
    const int wid = tid >> 5, lane = tid & 31;

    float lmax = -1e30f;
    for (int i = tid; i < N_; i += 256) {
        float v = s2[b * N_ + i];
        s2s[i] = v;
        lmax = fmaxf(lmax, v);
    }
#pragma unroll
    for (int o = 16; o > 0; o >>= 1)
        lmax = fmaxf(lmax, __shfl_xor_sync(0xffffffffu, lmax, o));
    if (lane == 0) wmax[wid] = lmax;
    __syncthreads();
    float s2max = wmax[0];
#pragma unroll
    for (int t = 1; t < 8; t++) s2max = fmaxf(s2max, wmax[t]);

    const int row = b * N_ + blockIdx.x * 8 + wid;
    const float s1i = s1[row];
    float xm = s1i + s2max;
    const float mhat = fmaxf(xm, 0.2f * xm);
    const uint32_t w = g_mask[row * 32 + lane];

    float l = 0.f;
#pragma unroll
    for (int t = 0; t < 32; t++) {
        uint32_t wt = __shfl_sync(0xffffffffu, w, t);
        float bf = (float)((wt >> lane) & 1u);
        float x = s1i + s2s[t * 32 + lane];
        float e = __expf(fmaxf(x, 0.2f * x) - mhat);
        l = fmaf(bf, e, l);
    }
#pragma unroll
    for (int o = 16; o > 0; o >>= 1)
        l += __shfl_xor_sync(0xffffffffu, l, o);
    if (lane == 0) {
        gm[row] = mhat;
        grl[row] = (l == 0.f) ? -1.f : 1.f / l;
    }
}

// ===================== attention via mma: out = P @ h ==================
__global__ void __launch_bounds__(256, 2) att_mma(
    const __half* __restrict__ h16,
    const float* __restrict__ s1, const float* __restrict__ s2,
    const float* __restrict__ m, const float* __restrict__ rl,
    __half* __restrict__ out16, float* __restrict__ outf)
{
    __shared__ __half As[64][40];
    __shared__ __half Bs[32][264];
    __shared__ float s2s[N_];
    __shared__ float s1s[64], ms[64], rls[64];

    const int tid = threadIdx.x, wid = tid >> 5, lane = tid & 31;
    const int wm = wid >> 2, wn = wid & 3;
    const int b = blockIdx.y, i0 = blockIdx.x * 64;

    for (int i = tid; i < N_; i += 256) s2s[i] = s2[b * N_ + i];
    if (tid < 64) {
        int r = b * N_ + i0 + tid;
        s1s[tid] = s1[r]; ms[tid] = m[r]; rls[tid] = rl[r];
    }
    __syncthreads();

    const uint32_t asu = smem_u32(&As[0][0]);
    const uint32_t bsu = smem_u32(&Bs[0][0]);

    float acc[2][8][4];
#pragma unroll
    for (int i = 0; i < 2; i++)
#pragma unroll
        for (int j = 0; j < 8; j++)
#pragma unroll
            for (int t = 0; t < 4; t++) acc[i][j][t] = 0.f;

    const int arow = tid >> 2, aseg = tid & 3;
    const int brow = tid >> 3, bseg = (tid & 7) * 32;
    const float s1r = s1s[arow], mr = ms[arow], rr_ = rls[arow];
    const uint8_t* mrow = (const uint8_t*)(g_mask + (size_t)(b * N_ + i0 + arow) * 32);

    uint4 pPk;        // P prefetch (8 halfs)
    uint4 bPk[4];     // H prefetch

    auto loadP = [&](int k0) {
        const int j0 = k0 + aseg * 8;
        uint32_t mb = mrow[j0 >> 3];                 // 8 mask bits
        float4 sv0 = *(const float4*)&s2s[j0];
        float4 sv1 = *(const float4*)&s2s[j0 + 4];
        float svs[8] = { sv0.x, sv0.y, sv0.z, sv0.w, sv1.x, sv1.y, sv1.z, sv1.w };
        float pv[8];
        if (rr_ < 0.f) {
#pragma unroll
            for (int t = 0; t < 8; t++) pv[t] = 1.0f / 1024.0f;
        } else {
#pragma unroll
            for (int t = 0; t < 8; t++) {
                float x = s1r + svs[t];
                float e = __expf(fmaxf(x, 0.2f * x) - mr) * rr_;
                pv[t] = ((mb >> t) & 1u) ? e : 0.f;
            }
        }
        __half2 h0 = __floats2half2_rn(pv[0], pv[1]);
        __half2 h1 = __floats2half2_rn(pv[2], pv[3]);
        __half2 h2 = __floats2half2_rn(pv[4], pv[5]);
        __half2 h3 = __floats2half2_rn(pv[6], pv[7]);
        pPk = make_uint4(*(uint32_t*)&h0, *(uint32_t*)&h1, *(uint32_t*)&h2, *(uint32_t*)&h3);
    };
    auto loadB = [&](int k0) {
        const uint4* src = (const uint4*)(h16 + (size_t)(b * N_ + k0 + brow) * H_ + bseg);
#pragma unroll
        for (int u = 0; u < 4; u++) bPk[u] = src[u];
    };
    auto stsTiles = [&]() {
        *(uint4*)&As[arow][aseg * 8] = pPk;
#pragma unroll
        for (int u = 0; u < 4; u++) *(uint4*)&Bs[brow][bseg + u * 8] = bPk[u];
    };
    auto compute = [&]() {
#pragma unroll
        for (int ksi = 0; ksi < 2; ksi++) {
            const int ksl = ksi * 16;
            uint32_t af[2][4];
#pragma unroll
            for (int mf = 0; mf < 2; mf++) {
                int r = wm * 32 + mf * 16 + (lane & 15);
                int c = ksl + (lane >> 4) * 8;
                ldsm_x4(af[mf][0], af[mf][1], af[mf][2], af[mf][3], asu + (r * 40 + c) * 2);
            }
            uint32_t bf[8][2];
#pragma unroll
            for (int ng = 0; ng < 4; ng++) {
                int r = ksl + (lane & 15);
                int c = wn * 64 + ng * 16 + (lane >> 4) * 8;
                ldsm_x4_t(bf[ng * 2][0], bf[ng * 2][1], bf[ng * 2 + 1][0], bf[ng * 2 + 1][1],
                          bsu + (r * 264 + c) * 2);
            }
#pragma unroll
            for (int mf = 0; mf < 2; mf++)
#pragma unroll
                for (int nf = 0; nf < 8; nf++)
                    mma16816(acc[mf][nf], af[mf], bf[nf]);
        }
    };

    loadP(0); loadB(0);
    for (int s = 0; s < 32; s++) {
        stsTiles();
        __syncthreads();
        if (s + 1 < 32) { loadP((s + 1) * 32); loadB((s + 1) * 32); }
        compute();
        __syncthreads();
    }

    // ---------------- epilogue: relu, write fp16 or fp32 ----------------
    const int r1 = lane >> 2, cq = (lane & 3) * 2;
#pragma unroll
    for (int mf = 0; mf < 2; mf++) {
#pragma unroll
        for (int rr = 0; rr < 2; rr++) {
            const int grow = b * N_ + i0 + wm * 32 + mf * 16 + r1 + rr * 8;
#pragma unroll
            for (int nf = 0; nf < 8; nf++) {
                const int col = wn * 64 + nf * 8 + cq;
                float e0 = fmaxf(acc[mf][nf][rr * 2],     0.f);
                float e1 = fmaxf(acc[mf][nf][rr * 2 + 1], 0.f);
                if (outf) {
                    float2 v = { e0, e1 };
                    *(float2*)(outf + (size_t)grow * H_ + col) = v;
                } else {
                    ((__half2*)out16)[((size_t)grow * H_ + col) >> 1] = __floats2half2_rn(e0, e1);
                }
            }
        }
    }
}

// ===================== pooling + MLP head =====================
__global__ void pool_partial(const float* __restrict__ x)
{
    const int b = blockIdx.y, ch = blockIdx.x, c = threadIdx.x;
    const float* p = x + (size_t)(b * N_ + ch * 128) * H_ + c;
    float s = 0.f, mx = -1e30f;
#pragma unroll 4
    for (int n = 0; n < 128; n++) {
        float v = p[(size_t)n * H_];
        s += v; mx = fmaxf(mx, v);
    }
    g_psum[(b * 8 + ch) * H_ + c] = s;
    g_pmax[(b * 8 + ch) * H_ + c] = mx;
}

__global__ void final_kernel(const float* __restrict__ W1, const float* __restrict__ b1,
                             const float* __restrict__ W2, const float* __restrict__ b2,
                             float* __restrict__ gout)
{
    __shared__ float gv[H_], g1[H_];
    const int b = blockIdx.x, c = threadIdx.x;
    float s = 0.f, mx = -1e30f;
#pragma unroll
    for (int ch = 0; ch < 8; ch++) {
        s += g_psum[(b * 8 + ch) * H_ + c];
        mx = fmaxf(mx, g_pmax[(b * 8 + ch) * H_ + c]);
    }
    gv[c] = s * (1.0f / N_) + mx;
    __syncthreads();
    float a = b1[c];
    for (int k = 0; k < H_; k++) a = fmaf(gv[k], W1[k * H_ + c], a);
    g1[c] = fmaxf(a, 0.f);
    __syncthreads();
    float a2 = b2[c];
    for (int k = 0; k < H_; k++) a2 = fmaf(g1[k], W2[k * H_ + c], a2);
    gout[b * H_ + c] = a2;
}

// ===================== launch =====================
extern "C" void kernel_launch(void* const* d_in, const int* in_sizes, int n_in,
                              void* d_out, int out_size)
{
    const float* nf   = (const float*)d_in[0];
    const float* adj  = (const float*)d_in[1];
    const float* embW = (const float*)d_in[2];
    const float* embb = (const float*)d_in[3];
    const float* W0   = (const float*)d_in[4];
    const float* a1_0 = (const float*)d_in[5];
    const float* a2_0 = (const float*)d_in[6];
    const float* W1   = (const float*)d_in[7];
    const float* a1_1 = (const float*)d_in[8];
    const float* a2_1 = (const float*)d_in[9];
    const float* gpW1 = (const float*)d_in[10];
    const float* gpb1 = (const float*)d_in[11];
    const float* gpW2 = (const float*)d_in[12];
    const float* gpb2 = (const float*)d_in[13];

    float* out  = (float*)d_out;
    float* outg = out + (size_t)B_ * N_ * H_;

    __half *px16b, *ph16, *pwf, *pw1;
    float *ps1, *ps2, *pm, *prl, *pbf;
    cudaGetSymbolAddress((void**)&px16b, g_x16b);
    cudaGetSymbolAddress((void**)&ph16,  g_h16);
    cudaGetSymbolAddress((void**)&pwf,   g_wf16);
    cudaGetSymbolAddress((void**)&pw1,   g_w116);
    cudaGetSymbolAddress((void**)&pbf,   g_bf);
    cudaGetSymbolAddress((void**)&ps1,   g_s1);
    cudaGetSymbolAddress((void**)&ps2,   g_s2);
    cudaGetSymbolAddress((void**)&pm,    g_m);
    cudaGetSymbolAddress((void**)&prl,   g_rl);

    const int M = B_ * N_;

    wfuse_kernel<<<FIN_ + 1, 256>>>(embW, embb, W0);
    prepw1_kernel<<<H_ * H_ / 256, 256>>>(W1);
    maskbuild_kernel<<<M / 8, 256>>>(adj);

    // ---- layer 1 (embed folded into Wf) ----
    hgemm_mma<FIN_, true><<<M / 64, 256>>>(nf, pwf, pbf, a1_0, a2_0, ph16, ps1, ps2);
    stat_kernel<<<dim3(N_ / 8, B_), 256>>>(ps1, ps2, pm, prl);
    att_mma<<<dim3(N_ / 64, B_), 256>>>(ph16, ps1, ps2, pm, prl, px16b, nullptr);

    // ---- layer 2 ----
    hgemm_mma<H_, false><<<M / 64, 256>>>(px16b, pw1, nullptr, a1_1, a2_1, ph16, ps1, ps2);
    stat_kernel<<<dim3(N_ / 8, B_), 256>>>(ps1, ps2, pm, prl);
    att_mma<<<dim3(N_ / 64, B_), 256>>>(ph16, ps1, ps2, pm, prl, nullptr, out);

    // ---- pooling + MLP head ----
    pool_partial<<<dim3(8, B_), 256>>>(out);
    final_kernel<<<B_, 256>>>(gpW1, gpb1, gpW2, gpb2, outg);
}

// round 5
// speedup vs baseline: 2.8178x; 1.0664x over previous
#include <cuda_runtime.h>
#include <cuda_fp16.h>
#include <cstdint>

#define B_ 16
#define N_ 1024
#define FIN_ 64
#define H_ 256
#define NEGV (-9e15f)

// ===================== scratch (static device globals) =====================
__device__ __half    g_x16b [B_ * N_ * H_];   // layer1 output (fp16)
__device__ __half    g_h16  [B_ * N_ * H_];   // h natural layout [b][j][c]
__device__ __half    g_wf16 [FIN_ * H_];      // fused emb@W0 (fp16)
__device__ float     g_bf   [H_];             // fused bias emb_b@W0
__device__ __half    g_w116 [H_ * H_];
__device__ uint32_t  g_mask [B_ * N_ * 32];   // 1 bit per adj entry
__device__ float     g_s1[B_ * N_], g_s2[B_ * N_], g_m[B_ * N_], g_rl[B_ * N_];
__device__ float     g_psum[B_ * 8 * H_], g_pmax[B_ * 8 * H_];

// ===================== mma/ldmatrix/cp.async helpers (baseline PTX) ============
__device__ __forceinline__ uint32_t smem_u32(const void* p) {
    uint32_t a;
    asm("{ .reg .u64 t; cvta.to.shared.u64 t, %1; cvt.u32.u64 %0, t; }" : "=r"(a) : "l"(p));
    return a;
}
__device__ __forceinline__ void ldsm_x4(uint32_t& r0, uint32_t& r1, uint32_t& r2,
                                        uint32_t& r3, uint32_t addr) {
    asm volatile("ldmatrix.sync.aligned.m8n8.x4.shared.b16 {%0,%1,%2,%3}, [%4];"
                 : "=r"(r0), "=r"(r1), "=r"(r2), "=r"(r3) : "r"(addr));
}
__device__ __forceinline__ void ldsm_x4_t(uint32_t& r0, uint32_t& r1, uint32_t& r2,
                                          uint32_t& r3, uint32_t addr) {
    asm volatile("ldmatrix.sync.aligned.m8n8.x4.trans.shared.b16 {%0,%1,%2,%3}, [%4];"
                 : "=r"(r0), "=r"(r1), "=r"(r2), "=r"(r3) : "r"(addr));
}
__device__ __forceinline__ void mma16816(float* d, const uint32_t* a, const uint32_t* b) {
    asm volatile("mma.sync.aligned.m16n8k16.row.col.f32.f16.f16.f32 "
                 "{%0,%1,%2,%3}, {%4,%5,%6,%7}, {%8,%9}, {%0,%1,%2,%3};"
                 : "+f"(d[0]), "+f"(d[1]), "+f"(d[2]), "+f"(d[3])
                 : "r"(a[0]), "r"(a[1]), "r"(a[2]), "r"(a[3]), "r"(b[0]), "r"(b[1]));
}
__device__ __forceinline__ void cp16(uint32_t saddr, const void* gaddr) {
    asm volatile("cp.async.cg.shared.global [%0], [%1], 16;" :: "r"(saddr), "l"(gaddr));
}
__device__ __forceinline__ void cp_commit() {
    asm volatile("cp.async.commit_group;" ::: "memory");
}
__device__ __forceinline__ void cp_wait0() {
    asm volatile("cp.async.wait_group 0;" ::: "memory");
}

// ===================== wfuse: Wf = emb@W0 (fp32), bf = emb_b@W0 =====================
__global__ void wfuse_kernel(const float* __restrict__ embW, const float* __restrict__ embb,
                             const float* __restrict__ W0)
{
    __shared__ float row[H_];
    const int f = blockIdx.x, o = threadIdx.x;
    row[o] = (f < FIN_) ? embW[f * H_ + o] : embb[o];
    __syncthreads();
    float acc = 0.f;
#pragma unroll 8
    for (int h = 0; h < H_; h++) acc = fmaf(row[h], W0[h * H_ + o], acc);
    if (f < FIN_) g_wf16[f * H_ + o] = __float2half(acc);
    else          g_bf[o] = acc;
}

__global__ void prepw1_kernel(const float* __restrict__ W1)
{
    int i = blockIdx.x * 256 + threadIdx.x;
    g_w116[i] = __float2half(W1[i]);
}

// ===================== mask build: adj fp32 -> bitmask =====================
__global__ void maskbuild_kernel(const float* __restrict__ adj)
{
    const int wid = threadIdx.x >> 5, lane = threadIdx.x & 31;
    const int row = blockIdx.x * 8 + wid;
    const float* ar = adj + (size_t)row * N_;
#pragma unroll
    for (int it = 0; it < 32; it++) {
        float a = ar[it * 32 + lane];
        unsigned w = __ballot_sync(0xffffffffu, a > 0.f);
        if (lane == 0) g_mask[row * 32 + it] = w;
    }
}

// ===================== hgemm: C[16384,256] = A[16384,K] @ Bw[K,256] (+bias) =====
// cp.async 2-stage pipeline; epilogue: h fp16 out + s1/s2 dots (fp32)
template <int KDIM, bool AFP32>
__global__ void __launch_bounds__(256, 2) hgemm_mma(
    const void* __restrict__ Araw, const __half* __restrict__ Bw,
    const float* __restrict__ bias, const float* __restrict__ a1v,
    const float* __restrict__ a2v,
    __half* __restrict__ out16, float* __restrict__ s1o, float* __restrict__ s2o)
{
    __shared__ __half As[2][64][40];
    __shared__ __half Bs[2][32][264];
    __shared__ float vb1[H_], vb2[H_], bb[H_];
    __shared__ float s1b[64], s2b[64];

    const int tid = threadIdx.x, wid = tid >> 5, lane = tid & 31;
    const int wm = wid >> 2, wn = wid & 3;
    const int row0 = blockIdx.x * 64;

    vb1[tid] = a1v[tid];
    vb2[tid] = a2v[tid];
    bb[tid]  = bias ? bias[tid] : 0.f;
    if (tid < 64) { s1b[tid] = 0.f; s2b[tid] = 0.f; }

    const uint32_t asu = smem_u32(&As[0][0][0]);
    const uint32_t bsu = smem_u32(&Bs[0][0][0]);
    constexpr uint32_t ASTG = 64 * 40 * 2;
    constexpr uint32_t BSTG = 32 * 264 * 2;

    float acc[2][8][4];
#pragma unroll
    for (int i = 0; i < 2; i++)
#pragma unroll
        for (int j = 0; j < 8; j++)
#pragma unroll
            for (int t = 0; t < 4; t++) acc[i][j][t] = 0.f;

    const int arow = tid >> 2, aseg = tid & 3;        // A: 64 rows x 32
    const int brow = tid >> 3, bseg = (tid & 7) * 32; // B: 32 rows x 256

    float4 aF0, aF1;   // fp32 A prefetch
    uint4  aPk;        // fp16 A prefetch

    auto loadA = [&](int k0) {
        if (AFP32) {
            const float* A = (const float*)Araw;
            const float* p = A + (size_t)(row0 + arow) * KDIM + k0 + aseg * 8;
            aF0 = *(const float4*)p;
            aF1 = *(const float4*)(p + 4);
        } else {
            const __half* A = (const __half*)Araw;
            aPk = *(const uint4*)(A + (size_t)(row0 + arow) * KDIM + k0 + aseg * 8);
        }
    };
    auto stsA = [&](int st) {
        uint32_t dst = asu + st * ASTG + (arow * 40 + aseg * 8) * 2;
        if (AFP32) {
            __half2 h0 = __floats2half2_rn(aF0.x, aF0.y);
            __half2 h1 = __floats2half2_rn(aF0.z, aF0.w);
            __half2 h2 = __floats2half2_rn(aF1.x, aF1.y);
            __half2 h3 = __floats2half2_rn(aF1.z, aF1.w);
            asm volatile("st.shared.v4.b32 [%0], {%1,%2,%3,%4};" :: "r"(dst),
                         "r"(*(uint32_t*)&h0), "r"(*(uint32_t*)&h1),
                         "r"(*(uint32_t*)&h2), "r"(*(uint32_t*)&h3) : "memory");
        } else {
            asm volatile("st.shared.v4.b32 [%0], {%1,%2,%3,%4};" :: "r"(dst),
                         "r"(aPk.x), "r"(aPk.y), "r"(aPk.z), "r"(aPk.w) : "memory");
        }
    };
    auto cpB = [&](int k0, int st) {
        const __half* src = Bw + (size_t)(k0 + brow) * H_ + bseg;
        uint32_t dst = bsu + st * BSTG + (brow * 264 + bseg) * 2;
#pragma unroll
        for (int u = 0; u < 4; u++) cp16(dst + u * 16, src + u * 8);
        cp_commit();
    };
    auto compute = [&](int buf) {
        const uint32_t asb = asu + buf * ASTG;
        const uint32_t bsb = bsu + buf * BSTG;
#pragma unroll
        for (int ksi = 0; ksi < 2; ksi++) {
            const int ksl = ksi * 16;
            uint32_t af[2][4];
#pragma unroll
            for (int mf = 0; mf < 2; mf++) {
                int r = wm * 32 + mf * 16 + (lane & 15);
                int c = ksl + (lane >> 4) * 8;
                ldsm_x4(af[mf][0], af[mf][1], af[mf][2], af[mf][3], asb + (r * 40 + c) * 2);
            }
            uint32_t bf[8][2];
#pragma unroll
            for (int ng = 0; ng < 4; ng++) {
                int r = ksl + (lane & 15);
                int c = wn * 64 + ng * 16 + (lane >> 4) * 8;
                ldsm_x4_t(bf[ng * 2][0], bf[ng * 2][1], bf[ng * 2 + 1][0], bf[ng * 2 + 1][1],
                          bsb + (r * 264 + c) * 2);
            }
#pragma unroll
            for (int mf = 0; mf < 2; mf++)
#pragma unroll
                for (int nf = 0; nf < 8; nf++)
                    mma16816(acc[mf][nf], af[mf], bf[nf]);
        }
    };

    constexpr int NK = KDIM / 32;
    loadA(0);
    stsA(0);
    cpB(0, 0);
    loadA(32);
#pragma unroll
    for (int s = 0; s < NK; s++) {
        const int buf = s & 1;
        cp_wait0();
        __syncthreads();
        if (s + 1 < NK) {
            stsA(buf ^ 1);
            cpB((s + 1) * 32, buf ^ 1);
            if (s + 2 < NK) loadA((s + 2) * 32);
        }
        compute(buf);
    }

    // ---------------- epilogue ----------------
    const int r1 = lane >> 2, cq = (lane & 3) * 2;
#pragma unroll
    for (int mf = 0; mf < 2; mf++) {
#pragma unroll
        for (int rr = 0; rr < 2; rr++) {
            const int rloc = wm * 32 + mf * 16 + r1 + rr * 8;
            const int grow = row0 + rloc;
            float p1 = 0.f, p2 = 0.f;
#pragma unroll
            for (int nf = 0; nf < 8; nf++) {
                const int col = wn * 64 + nf * 8 + cq;
                float e0 = acc[mf][nf][rr * 2]     + bb[col];
                float e1 = acc[mf][nf][rr * 2 + 1] + bb[col + 1];
                p1 = fmaf(e0, vb1[col], fmaf(e1, vb1[col + 1], p1));
                p2 = fmaf(e0, vb2[col], fmaf(e1, vb2[col + 1], p2));
                ((__half2*)out16)[((size_t)grow * H_ + col) >> 1] = __floats2half2_rn(e0, e1);
            }
            p1 += __shfl_xor_sync(0xffffffffu, p1, 1);
            p1 += __shfl_xor_sync(0xffffffffu, p1, 2);
            p2 += __shfl_xor_sync(0xffffffffu, p2, 1);
            p2 += __shfl_xor_sync(0xffffffffu, p2, 2);
            if ((lane & 3) == 0) {
                atomicAdd(&s1b[rloc], p1);
                atomicAdd(&s2b[rloc], p2);
            }
        }
    }
    __syncthreads();
    if (tid < 64) { s1o[row0 + tid] = s1b[tid]; s2o[row0 + tid] = s2b[tid]; }
}

// ===================== stat: single pass, shift by upper bound m̂ =====================
__global__ void stat_kernel(const float* __restrict__ s1, const float* __restrict__ s2,
                            float* __restrict__ gm, float* __restrict__ grl)
{
    __shared__ float s2s[N_];
    __shared__ float wmax[8];
    const int b = blockIdx.y, tid = threadIdx.x;
    const int wid = tid >> 5, lane = tid & 31;

    float lmax = -1e30f;
    for (int i = tid; i < N_; i += 256) {
        float v = s2[b * N_ + i];
        s2s[i] = v;
        lmax = fmaxf(lmax, v);
    }
#pragma unroll
    for (int o = 16; o > 0; o >>= 1)
        lmax = fmaxf(lmax, __shfl_xor_sync(0xffffffffu, lmax, o));
    if (lane == 0) wmax[wid] = lmax;
    __syncthreads();
    float s2max = wmax[0];
#pragma unroll
    for (int t = 1; t < 8; t++) s2max = fmaxf(s2max, wmax[t]);

    const int row = b * N_ + blockIdx.x * 8 + wid;
    const float s1i = s1[row];
    float xm = s1i + s2max;
    const float mhat = fmaxf(xm, 0.2f * xm);
    const uint32_t w = g_mask[row * 32 + lane];

    float l = 0.f;
#pragma unroll
    for (int t = 0; t < 32; t++) {
        uint32_t wt = __shfl_sync(0xffffffffu, w, t);
        float bf = (float)((wt >> lane) & 1u);
        float x = s1i + s2s[t * 32 + lane];
        float e = __expf(fmaxf(x, 0.2f * x) - mhat);
        l = fmaf(bf, e, l);
    }
#pragma unroll
    for (int o = 16; o > 0; o >>= 1)
        l += __shfl_xor_sync(0xffffffffu, l, o);
    if (lane == 0) {
        gm[row] = mhat;
        grl[row] = (l == 0.f) ? -1.f : 1.f / l;
    }
}

// ===================== attention via mma: out = P @ h (cp.async pipeline) =======
__global__ void __launch_bounds__(256, 2) att_mma(
    const __half* __restrict__ h16,
    const float* __restrict__ s1, const float* __restrict__ s2,
    const float* __restrict__ m, const float* __restrict__ rl,
    __half* __restrict__ out16, float* __restrict__ outf)
{
    __shared__ __half As[2][64][40];
    __shared__ __half Bs[2][32][264];

    const int tid = threadIdx.x, wid = tid >> 5, lane = tid & 31;
    const int wm = wid >> 2, wn = wid & 3;
    const int b = blockIdx.y, i0 = blockIdx.x * 64;

    const uint32_t asu = smem_u32(&As[0][0][0]);
    const uint32_t bsu = smem_u32(&Bs[0][0][0]);
    constexpr uint32_t ASTG = 64 * 40 * 2;
    constexpr uint32_t BSTG = 32 * 264 * 2;

    float acc[2][8][4];
#pragma unroll
    for (int i = 0; i < 2; i++)
#pragma unroll
        for (int j = 0; j < 8; j++)
#pragma unroll
            for (int t = 0; t < 4; t++) acc[i][j][t] = 0.f;

    const int arow = tid >> 2, aseg = tid & 3;
    const int brow = tid >> 3, bseg = (tid & 7) * 32;

    // per-thread row scalars straight from GMEM (4 threads/row -> L1 broadcast)
    const int grow_a = b * N_ + i0 + arow;
    const float s1r = s1[grow_a];
    const float mr  = m[grow_a];
    const float rr_ = rl[grow_a];
    const uint8_t* mrow = (const uint8_t*)(g_mask + (size_t)grow_a * 32);
    const float* s2g = s2 + b * N_;

    uint4 pPk;

    auto loadP = [&](int k0) {
        const int j0 = k0 + aseg * 8;
        uint32_t mb = mrow[j0 >> 3];
        float4 sv0 = *(const float4*)(s2g + j0);
        float4 sv1 = *(const float4*)(s2g + j0 + 4);
        float svs[8] = { sv0.x, sv0.y, sv0.z, sv0.w, sv1.x, sv1.y, sv1.z, sv1.w };
        float pv[8];
        if (rr_ < 0.f) {
#pragma unroll
            for (int t = 0; t < 8; t++) pv[t] = 1.0f / 1024.0f;
        } else {
#pragma unroll
            for (int t = 0; t < 8; t++) {
                float x = s1r + svs[t];
                float e = __expf(fmaxf(x, 0.2f * x) - mr) * rr_;
                pv[t] = ((mb >> t) & 1u) ? e : 0.f;
            }
        }
        __half2 h0 = __floats2half2_rn(pv[0], pv[1]);
        __half2 h1 = __floats2half2_rn(pv[2], pv[3]);
        __half2 h2 = __floats2half2_rn(pv[4], pv[5]);
        __half2 h3 = __floats2half2_rn(pv[6], pv[7]);
        pPk = make_uint4(*(uint32_t*)&h0, *(uint32_t*)&h1, *(uint32_t*)&h2, *(uint32_t*)&h3);
    };
    auto stsP = [&](int st) {
        uint32_t dst = asu + st * ASTG + (arow * 40 + aseg * 8) * 2;
        asm volatile("st.shared.v4.b32 [%0], {%1,%2,%3,%4};" :: "r"(dst),
                     "r"(pPk.x), "r"(pPk.y), "r"(pPk.z), "r"(pPk.w) : "memory");
    };
    auto cpB = [&](int k0, int st) {
        const __half* src = h16 + (size_t)(b * N_ + k0 + brow) * H_ + bseg;
        uint32_t dst = bsu + st * BSTG + (brow * 264 + bseg) * 2;
#pragma unroll
        for (int u = 0; u < 4; u++) cp16(dst + u * 16, src + u * 8);
        cp_commit();
    };
    auto compute = [&](int buf) {
        const uint32_t asb = asu + buf * ASTG;
        const uint32_t bsb = bsu + buf * BSTG;
#pragma unroll
        for (int ksi = 0; ksi < 2; ksi++) {
            const int ksl = ksi * 16;
            uint32_t af[2][4];
#pragma unroll
            for (int mf = 0; mf < 2; mf++) {
                int r = wm * 32 + mf * 16 + (lane & 15);
                int c = ksl + (lane >> 4) * 8;
                ldsm_x4(af[mf][0], af[mf][1], af[mf][2], af[mf][3], asb + (r * 40 + c) * 2);
            }
            uint32_t bf[8][2];
#pragma unroll
            for (int ng = 0; ng < 4; ng++) {
                int r = ksl + (lane & 15);
                int c = wn * 64 + ng * 16 + (lane >> 4) * 8;
                ldsm_x4_t(bf[ng * 2][0], bf[ng * 2][1], bf[ng * 2 + 1][0], bf[ng * 2 + 1][1],
                          bsb + (r * 264 + c) * 2);
            }
#pragma unroll
            for (int mf = 0; mf < 2; mf++)
#pragma unroll
                for (int nf = 0; nf < 8; nf++)
                    mma16816(acc[mf][nf], af[mf], bf[nf]);
        }
    };

    constexpr int NK = N_ / 32;   // 32
    loadP(0);
    stsP(0);
    cpB(0, 0);
    loadP(32);
    for (int s = 0; s < NK; s++) {
        const int buf = s & 1;
        cp_wait0();
        __syncthreads();
        if (s + 1 < NK) {
            stsP(buf ^ 1);
            cpB((s + 1) * 32, buf ^ 1);
            if (s + 2 < NK) loadP((s + 2) * 32);
        }
        compute(buf);
    }

    // ---------------- epilogue: relu, write fp16 or fp32 ----------------
    const int r1 = lane >> 2, cq = (lane & 3) * 2;
#pragma unroll
    for (int mf = 0; mf < 2; mf++) {
#pragma unroll
        for (int rr = 0; rr < 2; rr++) {
            const int grow = b * N_ + i0 + wm * 32 + mf * 16 + r1 + rr * 8;
#pragma unroll
            for (int nf = 0; nf < 8; nf++) {
                const int col = wn * 64 + nf * 8 + cq;
                float e0 = fmaxf(acc[mf][nf][rr * 2],     0.f);
                float e1 = fmaxf(acc[mf][nf][rr * 2 + 1], 0.f);
                if (outf) {
                    float2 v = { e0, e1 };
                    *(float2*)(outf + (size_t)grow * H_ + col) = v;
                } else {
                    ((__half2*)out16)[((size_t)grow * H_ + col) >> 1] = __floats2half2_rn(e0, e1);
                }
            }
        }
    }
}

// ===================== pooling + MLP head =====================
__global__ void pool_partial(const float* __restrict__ x)
{
    const int b = blockIdx.y, ch = blockIdx.x, c = threadIdx.x;
    const float* p = x + (size_t)(b * N_ + ch * 128) * H_ + c;
    float s = 0.f, mx = -1e30f;
#pragma unroll 4
    for (int n = 0; n < 128; n++) {
        float v = p[(size_t)n * H_];
        s += v; mx = fmaxf(mx, v);
    }
    g_psum[(b * 8 + ch) * H_ + c] = s;
    g_pmax[(b * 8 + ch) * H_ + c] = mx;
}

__global__ void final_kernel(const float* __restrict__ W1, const float* __restrict__ b1,
                             const float* __restrict__ W2, const float* __restrict__ b2,
                             float* __restrict__ gout)
{
    __shared__ float gv[H_], g1[H_];
    const int b = blockIdx.x, c = threadIdx.x;
    float s = 0.f, mx = -1e30f;
#pragma unroll
    for (int ch = 0; ch < 8; ch++) {
        s += g_psum[(b * 8 + ch) * H_ + c];
        mx = fmaxf(mx, g_pmax[(b * 8 + ch) * H_ + c]);
    }
    gv[c] = s * (1.0f / N_) + mx;
    __syncthreads();
    float a = b1[c];
    for (int k = 0; k < H_; k++) a = fmaf(gv[k], W1[k * H_ + c], a);
    g1[c] = fmaxf(a, 0.f);
    __syncthreads();
    float a2 = b2[c];
    for (int k = 0; k < H_; k++) a2 = fmaf(g1[k], W2[k * H_ + c], a2);
    gout[b * H_ + c] = a2;
}

// ===================== launch =====================
extern "C" void kernel_launch(void* const* d_in, const int* in_sizes, int n_in,
                              void* d_out, int out_size)
{
    const float* nf   = (const float*)d_in[0];
    const float* adj  = (const float*)d_in[1];
    const float* embW = (const float*)d_in[2];
    const float* embb = (const float*)d_in[3];
    const float* W0   = (const float*)d_in[4];
    const float* a1_0 = (const float*)d_in[5];
    const float* a2_0 = (const float*)d_in[6];
    const float* W1   = (const float*)d_in[7];
    const float* a1_1 = (const float*)d_in[8];
    const float* a2_1 = (const float*)d_in[9];
    const float* gpW1 = (const float*)d_in[10];
    const float* gpb1 = (const float*)d_in[11];
    const float* gpW2 = (const float*)d_in[12];
    const float* gpb2 = (const float*)d_in[13];

    float* out  = (float*)d_out;
    float* outg = out + (size_t)B_ * N_ * H_;

    __half *px16b, *ph16, *pwf, *pw1;
    float *ps1, *ps2, *pm, *prl, *pbf;
    cudaGetSymbolAddress((void**)&px16b, g_x16b);
    cudaGetSymbolAddress((void**)&ph16,  g_h16);
    cudaGetSymbolAddress((void**)&pwf,   g_wf16);
    cudaGetSymbolAddress((void**)&pw1,   g_w116);
    cudaGetSymbolAddress((void**)&pbf,   g_bf);
    cudaGetSymbolAddress((void**)&ps1,   g_s1);
    cudaGetSymbolAddress((void**)&ps2,   g_s2);
    cudaGetSymbolAddress((void**)&pm,    g_m);
    cudaGetSymbolAddress((void**)&prl,   g_rl);

    const int M = B_ * N_;

    wfuse_kernel<<<FIN_ + 1, 256>>>(embW, embb, W0);
    prepw1_kernel<<<H_ * H_ / 256, 256>>>(W1);
    maskbuild_kernel<<<M / 8, 256>>>(adj);

    // ---- layer 1 (embed folded into Wf) ----
    hgemm_mma<FIN_, true><<<M / 64, 256>>>(nf, pwf, pbf, a1_0, a2_0, ph16, ps1, ps2);
    stat_kernel<<<dim3(N_ / 8, B_), 256>>>(ps1, ps2, pm, prl);
    att_mma<<<dim3(N_ / 64, B_), 256>>>(ph16, ps1, ps2, pm, prl, px16b, nullptr);

    // ---- layer 2 ----
    hgemm_mma<H_, false><<<M / 64, 256>>>(px16b, pw1, nullptr, a1_1, a2_1, ph16, ps1, ps2);
    stat_kernel<<<dim3(N_ / 8, B_), 256>>>(ps1, ps2, pm, prl);
    att_mma<<<dim3(N_ / 64, B_), 256>>>(ph16, ps1, ps2, pm, prl, nullptr, out);

    // ---- pooling + MLP head ----
    pool_partial<<<dim3(8, B_), 256>>>(out);
    final_kernel<<<B_, 256>>>(gpW1, gpb1, gpW2, gpb2, outg);
}